// round 15
// baseline (speedup 1.0000x reference)
#include <cuda_runtime.h>
#include <cuda_bf16.h>

#define NUM_CLASSES 16384
#define FEAT_DIM    1024
#define ALPHA       0.5f

// Scratch (zero at process start; prep_kernel re-establishes it every replay:
// counts zeroed in phase 1, barrier counters self-reset at depart).
__device__ int          g_counts[NUM_CLASSES];
__device__ unsigned int g_arrive;
__device__ unsigned int g_depart;

// ---------------------------------------------------------------------------
// K0: prep. 128 blocks x 128 threads, ALL co-resident (128 <= 148 SMs) so the
// intra-kernel spin barrier cannot deadlock.
//   phase 1: zero counts + out[0]
//   barrier: release-arrive, acquire-spin
//   phase 2: bincount (one sample per thread)
//   depart:  last block resets barrier counters for the next graph replay
// ---------------------------------------------------------------------------
__global__ __launch_bounds__(128)
void prep_kernel(const int* __restrict__ y_true, float* __restrict__ out) {
    const int tid = threadIdx.x;
    const int b   = blockIdx.x;
    const int i   = b * 128 + tid;

    g_counts[i] = 0;
    if (i == 0) out[0] = 0.0f;
    __syncthreads();

    if (tid == 0) {
        unsigned int old;
        asm volatile("atom.add.release.gpu.global.u32 %0, [%1], 1;"
                     : "=r"(old) : "l"(&g_arrive) : "memory");
        unsigned int v = 0;
        do {
            asm volatile("ld.acquire.gpu.global.u32 %0, [%1];"
                         : "=r"(v) : "l"(&g_arrive) : "memory");
        } while (v < 128u);
    }
    __syncthreads();

    atomicAdd(&g_counts[y_true[i]], 1);
    __syncthreads();

    if (tid == 0) {
        unsigned int old = atomicAdd(&g_depart, 1u);
        if (old == 127u) { g_arrive = 0u; g_depart = 0u; }
    }
}

// ---------------------------------------------------------------------------
// K1: the R3-proven main kernel + direct RED into out (no combine kernel).
// One block (128 thr) per row, 8 independent LDG.128 per thread.
//   j  = y_true[i], jj = y_true[j], s = ALPHA/(counts[jj]+1)   (counts final)
//   d  = y_pred[i] - centers[j] + s*(centers[jj] - y_pred[j])
//   out += sum(d^2) / (B*D)      (single float RED per block)
// ---------------------------------------------------------------------------
__global__ __launch_bounds__(128)
void centerloss_kernel(const int*   __restrict__ y_true,
                       const float* __restrict__ y_pred,
                       const float* __restrict__ centers,
                       float*       __restrict__ out) {
    const int row = blockIdx.x;
    const int tid = threadIdx.x;

    const int j  = y_true[row];
    const int jj = y_true[j];
    const float scale = ALPHA / ((float)g_counts[jj] + 1.0f);

    const float4* A = (const float4*)(y_pred  + (size_t)row * FEAT_DIM);
    const float4* B = (const float4*)(centers + (size_t)j   * FEAT_DIM);
    const float4* C = (const float4*)(centers + (size_t)jj  * FEAT_DIM);
    const float4* D = (const float4*)(y_pred  + (size_t)j   * FEAT_DIM);

    const int t0 = tid;
    const int t1 = tid + 128;

    // front-batched: 8 independent 16B loads
    float4 a0 = A[t0], a1 = A[t1];
    float4 b0 = B[t0], b1 = B[t1];
    float4 c0 = C[t0], c1 = C[t1];
    float4 d0 = D[t0], d1 = D[t1];

    float s = 0.0f;
    {
        float dx = a0.x - b0.x + scale * (c0.x - d0.x);
        float dy = a0.y - b0.y + scale * (c0.y - d0.y);
        float dz = a0.z - b0.z + scale * (c0.z - d0.z);
        float dw = a0.w - b0.w + scale * (c0.w - d0.w);
        s += dx*dx + dy*dy + dz*dz + dw*dw;
    }
    {
        float dx = a1.x - b1.x + scale * (c1.x - d1.x);
        float dy = a1.y - b1.y + scale * (c1.y - d1.y);
        float dz = a1.z - b1.z + scale * (c1.z - d1.z);
        float dw = a1.w - b1.w + scale * (c1.w - d1.w);
        s += dx*dx + dy*dy + dz*dz + dw*dw;
    }

    // warp reduce
    #pragma unroll
    for (int off = 16; off > 0; off >>= 1)
        s += __shfl_xor_sync(0xFFFFFFFFu, s, off);

    // block reduce (4 warps)
    __shared__ float warp_sums[4];
    const int wid = tid >> 5;
    const int lid = tid & 31;
    if (lid == 0) warp_sums[wid] = s;
    __syncthreads();

    if (tid == 0) {
        const double INV = 1.0 / ((double)NUM_CLASSES * (double)FEAT_DIM);
        double v = (double)warp_sums[0] + (double)warp_sums[1]
                 + (double)warp_sums[2] + (double)warp_sums[3];
        atomicAdd(out, (float)(v * INV));   // single RED per block, no tail
    }
}

extern "C" void kernel_launch(void* const* d_in, const int* in_sizes, int n_in,
                              void* d_out, int out_size) {
    const int*   y_true  = (const int*)  d_in[0];
    const float* y_pred  = (const float*)d_in[1];
    const float* centers = (const float*)d_in[2];
    float* out = (float*)d_out;

    prep_kernel<<<128, 128>>>(y_true, out);
    centerloss_kernel<<<NUM_CLASSES, 128>>>(y_true, y_pred, centers, out);
}

// round 16
// speedup vs baseline: 1.1309x; 1.1309x over previous
#include <cuda_runtime.h>
#include <cuda_bf16.h>

#define NUM_CLASSES 16384
#define FEAT_DIM    1024
#define ALPHA       0.5f
#define NSLOT       64
#define FSTRIDE     32   // 32 floats = 128 B -> distinct LTS partitions
#define USTRIDE     32   // 32 uints  = 128 B

// Scratch (zero at process start). Self-cleaning per replay:
//   counts: zeroed by prep phase 1
//   slots/tickets: reset by the 256th arriver of each slot inside K1
__device__ int          g_counts[NUM_CLASSES];
__device__ float        g_slot[NSLOT * FSTRIDE];
__device__ unsigned int g_stick[NSLOT * USTRIDE];
__device__ unsigned int g_arrive;
__device__ unsigned int g_depart;

// ---------------------------------------------------------------------------
// K0: prep. 128 blocks x 128 threads, ALL co-resident (128 <= 148 SMs) so the
// intra-kernel spin barrier cannot deadlock.
//   phase 1: zero counts + out[0];  barrier;  phase 2: bincount
//   depart: last block resets barrier counters for the next replay
// ---------------------------------------------------------------------------
__global__ __launch_bounds__(128)
void prep_kernel(const int* __restrict__ y_true, float* __restrict__ out) {
    const int tid = threadIdx.x;
    const int i   = blockIdx.x * 128 + tid;

    g_counts[i] = 0;
    if (i == 0) out[0] = 0.0f;
    __syncthreads();

    if (tid == 0) {
        unsigned int old;
        asm volatile("atom.add.release.gpu.global.u32 %0, [%1], 1;"
                     : "=r"(old) : "l"(&g_arrive) : "memory");
        unsigned int v = 0;
        do {
            asm volatile("ld.acquire.gpu.global.u32 %0, [%1];"
                         : "=r"(v) : "l"(&g_arrive) : "memory");
        } while (v < 128u);
    }
    __syncthreads();

    atomicAdd(&g_counts[y_true[i]], 1);
    __syncthreads();

    if (tid == 0) {
        unsigned int old = atomicAdd(&g_depart, 1u);
        if (old == 127u) { g_arrive = 0u; g_depart = 0u; }
    }
}

// ---------------------------------------------------------------------------
// K1: R8-proven body + hierarchical SPREAD finalize (no combine kernel).
// One block (128 thr) per row, 8 independent LDG.128 per thread.
//   j  = y_true[i], jj = y_true[j], s = ALPHA/(counts[jj]+1)   (counts final)
//   d  = y_pred[i] - centers[j] + s*(centers[jj] - y_pred[j])
// Finalize: block REDs (sum d^2)*INV into g_slot[row&63] (64 strided floats),
// then acq_rel-tickets g_stick[row&63] (64 strided addresses, 256 arrivals
// each — NEVER a single hot address, the R2/R4/R15 poison). The 256th
// arriver per slot atomicExch-drains the slot into ONE RED on out (64 total)
// and resets the slot/ticket for the next graph replay.
// ---------------------------------------------------------------------------
__global__ __launch_bounds__(128)
void centerloss_kernel(const int*   __restrict__ y_true,
                       const float* __restrict__ y_pred,
                       const float* __restrict__ centers,
                       float*       __restrict__ out) {
    const int row = blockIdx.x;
    const int tid = threadIdx.x;

    const int j  = y_true[row];
    const int jj = y_true[j];
    const float scale = ALPHA / ((float)g_counts[jj] + 1.0f);

    const float4* A = (const float4*)(y_pred  + (size_t)row * FEAT_DIM);
    const float4* B = (const float4*)(centers + (size_t)j   * FEAT_DIM);
    const float4* C = (const float4*)(centers + (size_t)jj  * FEAT_DIM);
    const float4* D = (const float4*)(y_pred  + (size_t)j   * FEAT_DIM);

    const int t0 = tid;
    const int t1 = tid + 128;

    // front-batched: 8 independent 16B loads
    float4 a0 = A[t0], a1 = A[t1];
    float4 b0 = B[t0], b1 = B[t1];
    float4 c0 = C[t0], c1 = C[t1];
    float4 d0 = D[t0], d1 = D[t1];

    float s = 0.0f;
    {
        float dx = a0.x - b0.x + scale * (c0.x - d0.x);
        float dy = a0.y - b0.y + scale * (c0.y - d0.y);
        float dz = a0.z - b0.z + scale * (c0.z - d0.z);
        float dw = a0.w - b0.w + scale * (c0.w - d0.w);
        s += dx*dx + dy*dy + dz*dz + dw*dw;
    }
    {
        float dx = a1.x - b1.x + scale * (c1.x - d1.x);
        float dy = a1.y - b1.y + scale * (c1.y - d1.y);
        float dz = a1.z - b1.z + scale * (c1.z - d1.z);
        float dw = a1.w - b1.w + scale * (c1.w - d1.w);
        s += dx*dx + dy*dy + dz*dz + dw*dw;
    }

    // warp reduce
    #pragma unroll
    for (int off = 16; off > 0; off >>= 1)
        s += __shfl_xor_sync(0xFFFFFFFFu, s, off);

    // block reduce (4 warps)
    __shared__ float warp_sums[4];
    const int wid = tid >> 5;
    const int lid = tid & 31;
    if (lid == 0) warp_sums[wid] = s;
    __syncthreads();

    if (tid == 0) {
        const float INV = (float)(1.0 / ((double)NUM_CLASSES * (double)FEAT_DIM));
        float v = (warp_sums[0] + warp_sums[1] + warp_sums[2] + warp_sums[3]) * INV;

        const int slot = row & (NSLOT - 1);
        float* sp        = &g_slot[slot * FSTRIDE];
        unsigned int* tp = &g_stick[slot * USTRIDE];

        atomicAdd(sp, v);                       // spread float RED (64 addrs)
        unsigned int old;
        asm volatile("atom.acq_rel.gpu.global.add.u32 %0, [%1], 1;"
                     : "=r"(old) : "l"(tp) : "memory");
        if (old == (NUM_CLASSES / NSLOT) - 1) { // 256th arriver on this slot
            float tot = atomicExch(sp, 0.0f);   // drain + reset (L2-coherent)
            atomicAdd(out, tot);                // 64 REDs total on out
            *tp = 0u;                           // ticket reset for next replay
        }
    }
}

extern "C" void kernel_launch(void* const* d_in, const int* in_sizes, int n_in,
                              void* d_out, int out_size) {
    const int*   y_true  = (const int*)  d_in[0];
    const float* y_pred  = (const float*)d_in[1];
    const float* centers = (const float*)d_in[2];
    float* out = (float*)d_out;

    prep_kernel<<<128, 128>>>(y_true, out);
    centerloss_kernel<<<NUM_CLASSES, 128>>>(y_true, y_pred, centers, out);
}

// round 17
// speedup vs baseline: 1.2884x; 1.1393x over previous
#include <cuda_runtime.h>
#include <cuda_bf16.h>

#define NUM_CLASSES 16384
#define FEAT_DIM    1024
#define ALPHA       0.5f
#define NSLOT       64
#define FSTRIDE     32   // 32 floats = 128 B -> distinct LTS partitions
#define USTRIDE     32   // 32 uints  = 128 B

// Scratch (zero at process start). Self-cleaning per replay:
//   counts: zeroed by prep phase 1
//   slots/tickets: reset by the 256th arriver of each slot inside K1
__device__ int          g_counts[NUM_CLASSES];
__device__ float        g_slot[NSLOT * FSTRIDE];
__device__ unsigned int g_stick[NSLOT * USTRIDE];
__device__ unsigned int g_arrive;
__device__ unsigned int g_depart;

// ---------------------------------------------------------------------------
// K0: prep. 128 blocks x 128 threads, ALL co-resident (128 <= 148 SMs) so the
// intra-kernel spin barrier cannot deadlock.
//   phase 1: zero counts + out[0];  barrier;  phase 2: bincount
//   depart: last block resets barrier counters for the next replay
// ---------------------------------------------------------------------------
__global__ __launch_bounds__(128)
void prep_kernel(const int* __restrict__ y_true, float* __restrict__ out) {
    const int tid = threadIdx.x;
    const int i   = blockIdx.x * 128 + tid;

    g_counts[i] = 0;
    if (i == 0) out[0] = 0.0f;
    __syncthreads();

    if (tid == 0) {
        unsigned int old;
        asm volatile("atom.add.release.gpu.global.u32 %0, [%1], 1;"
                     : "=r"(old) : "l"(&g_arrive) : "memory");
        unsigned int v = 0;
        do {
            asm volatile("ld.acquire.gpu.global.u32 %0, [%1];"
                         : "=r"(v) : "l"(&g_arrive) : "memory");
        } while (v < 128u);
    }
    __syncthreads();

    atomicAdd(&g_counts[y_true[i]], 1);
    __syncthreads();

    if (tid == 0) {
        unsigned int old = atomicAdd(&g_depart, 1u);
        if (old == 127u) { g_arrive = 0u; g_depart = 0u; }
    }
}

// ---------------------------------------------------------------------------
// K1: R8-proven body + inline scale + spread-ticket finalize,
// REGISTER-CAPPED via __launch_bounds__(128, 16) -> <=32 regs, so the tail
// cannot tax occupancy (the R4/R16 poison). Tail extras spill to local —
// executed once per block by one thread, cost ~nil.
//   j = y_true[i], jj = y_true[j], s = ALPHA/(counts[jj]+1)  (counts final)
//   d = y_pred[i] - centers[j] + s*(centers[jj] - y_pred[j])
// Block REDs (sum d^2)*INV into g_slot[row&63]; 64 spread acq_rel tickets;
// the 256th arriver per slot drains it with one RED into out (64 total).
// ---------------------------------------------------------------------------
__global__ __launch_bounds__(128, 16)
void centerloss_kernel(const int*   __restrict__ y_true,
                       const float* __restrict__ y_pred,
                       const float* __restrict__ centers,
                       float*       __restrict__ out) {
    const int row = blockIdx.x;
    const int tid = threadIdx.x;

    const int j  = y_true[row];
    const int jj = y_true[j];
    const float scale = ALPHA / ((float)g_counts[jj] + 1.0f);

    const float4* A = (const float4*)(y_pred  + (size_t)row * FEAT_DIM);
    const float4* B = (const float4*)(centers + (size_t)j   * FEAT_DIM);
    const float4* C = (const float4*)(centers + (size_t)jj  * FEAT_DIM);
    const float4* D = (const float4*)(y_pred  + (size_t)j   * FEAT_DIM);

    const int t0 = tid;
    const int t1 = tid + 128;

    // front-batched: 8 independent 16B loads
    float4 a0 = A[t0], a1 = A[t1];
    float4 b0 = B[t0], b1 = B[t1];
    float4 c0 = C[t0], c1 = C[t1];
    float4 d0 = D[t0], d1 = D[t1];

    float s = 0.0f;
    {
        float dx = a0.x - b0.x + scale * (c0.x - d0.x);
        float dy = a0.y - b0.y + scale * (c0.y - d0.y);
        float dz = a0.z - b0.z + scale * (c0.z - d0.z);
        float dw = a0.w - b0.w + scale * (c0.w - d0.w);
        s += dx*dx + dy*dy + dz*dz + dw*dw;
    }
    {
        float dx = a1.x - b1.x + scale * (c1.x - d1.x);
        float dy = a1.y - b1.y + scale * (c1.y - d1.y);
        float dz = a1.z - b1.z + scale * (c1.z - d1.z);
        float dw = a1.w - b1.w + scale * (c1.w - d1.w);
        s += dx*dx + dy*dy + dz*dz + dw*dw;
    }

    // warp reduce
    #pragma unroll
    for (int off = 16; off > 0; off >>= 1)
        s += __shfl_xor_sync(0xFFFFFFFFu, s, off);

    // block reduce (4 warps)
    __shared__ float warp_sums[4];
    const int wid = tid >> 5;
    const int lid = tid & 31;
    if (lid == 0) warp_sums[wid] = s;
    __syncthreads();

    if (tid == 0) {
        const float INV = (float)(1.0 / ((double)NUM_CLASSES * (double)FEAT_DIM));
        float v = (warp_sums[0] + warp_sums[1] + warp_sums[2] + warp_sums[3]) * INV;

        const int slot = row & (NSLOT - 1);
        float* sp        = &g_slot[slot * FSTRIDE];
        unsigned int* tp = &g_stick[slot * USTRIDE];

        atomicAdd(sp, v);                       // spread float RED (64 addrs)
        unsigned int old;
        asm volatile("atom.acq_rel.gpu.global.add.u32 %0, [%1], 1;"
                     : "=r"(old) : "l"(tp) : "memory");
        if (old == (NUM_CLASSES / NSLOT) - 1) { // 256th arriver on this slot
            float tot = atomicExch(sp, 0.0f);   // drain + reset (L2-coherent)
            atomicAdd(out, tot);                // 64 REDs total on out
            *tp = 0u;                           // ticket reset for next replay
        }
    }
}

extern "C" void kernel_launch(void* const* d_in, const int* in_sizes, int n_in,
                              void* d_out, int out_size) {
    const int*   y_true  = (const int*)  d_in[0];
    const float* y_pred  = (const float*)d_in[1];
    const float* centers = (const float*)d_in[2];
    float* out = (float*)d_out;

    prep_kernel<<<128, 128>>>(y_true, out);
    centerloss_kernel<<<NUM_CLASSES, 128>>>(y_true, y_pred, centers, out);
}